// round 7
// baseline (speedup 1.0000x reference)
#include <cuda_runtime.h>
#include <cuda_bf16.h>

#define QN      400
#define PN      200000
#define NLAB    100
#define KS      4
#define THREADS 128
#define CHUNK   (PN / KS)                 // 50000
#define BINW    (NLAB * THREADS)          // 12800 bf16x2 bins = 50 KB
#define CVT_BLOCKS ((PN / 4 + 255) / 256) // 196

// ---------------- device scratch (no allocation allowed) ----------------
__device__ unsigned char g_lab8[PN];
__device__ int   g_blockhist[CVT_BLOCKS * NLAB];
__device__ float g_partial[KS * QN * NLAB * 2];   // [r][q][lab][{d,s}]
__device__ float g_totals[KS * QN * 2];           // [r][q][{f0tot, ptot}]

// ---------------- kernel 0: narrow labels to u8 + per-block histogram ----------------
__global__ void convert_labels(const int* __restrict__ labels) {
    __shared__ int hist[NLAB];
    const int tid = threadIdx.x;
    for (int i = tid; i < NLAB; i += 256) hist[i] = 0;
    __syncthreads();

    int i = blockIdx.x * blockDim.x + tid;
    int base = i * 4;
    if (base < PN) {
        int4 l = *(const int4*)(labels + base);
        uchar4 u;
        u.x = (unsigned char)l.x; u.y = (unsigned char)l.y;
        u.z = (unsigned char)l.z; u.w = (unsigned char)l.w;
        *(uchar4*)(g_lab8 + base) = u;
        atomicAdd(&hist[l.x], 1); atomicAdd(&hist[l.y], 1);
        atomicAdd(&hist[l.z], 1); atomicAdd(&hist[l.w], 1);
    }
    __syncthreads();
    for (int j = tid; j < NLAB; j += 256)
        g_blockhist[blockIdx.x * NLAB + j] = hist[j];
}

// ---- branch-free transform: 3 MUFU, no selects. Safe for |x| < 80. ----
__device__ __forceinline__ void xform(float x, float& d, float& p, float& f0) {
    float t, lg;
    asm("ex2.approx.f32 %0, %1;" : "=f"(t) : "f"(x * -1.4426950408889634f)); // e^-x
    float opt = 1.0f + t;
    asm("rcp.approx.f32 %0, %1;" : "=f"(p)  : "f"(opt));   // p = sigmoid(x)
    asm("lg2.approx.f32 %0, %1;" : "=f"(lg) : "f"(opt));
    float logp = lg * -0.69314718055994531f;               // log sigmoid(x)
    float l1mp = logp - x;                                 // log sigmoid(-x)
    float omp  = t * p;                                    // 1 - p, exact identity
    f0 = (p * p) * (l1mp * -0.75f);
    float f1 = (omp * omp) * (logp * -0.25f);
    d = f1 - f0;
}

// ---------------- kernel 1: main segmented reduction (2-deep pipeline) ----------------
__global__ __launch_bounds__(THREADS, 4)
void main_kernel(const float* __restrict__ pred) {
    extern __shared__ __nv_bfloat162 sb[];   // [NLAB][THREADS], bank = tid%32
    const int tid = threadIdx.x;
    const int q = blockIdx.x;
    const int r = blockIdx.y;

    uint4* z4 = (uint4*)sb;
    #pragma unroll 4
    for (int i = tid; i < BINW / 4; i += THREADS)
        z4[i] = make_uint4(0u, 0u, 0u, 0u);
    __syncthreads();

    const float* row = pred + (size_t)q * PN + (size_t)r * CHUNK;
    const unsigned char* lab = g_lab8 + r * CHUNK;
    __nv_bfloat162* const bbase = sb + tid;

    float accf0a = 0.f, accf0b = 0.f;
    const int S = THREADS * 8;

    // ---- pipeline prologue: load iter0, prefetch iter1, compute iter0 (no RMW) ----
    int idx = tid * 8;                            // always < CHUNK
    float4 va = __ldcs((const float4*)(row + idx));
    float4 vb = __ldcs((const float4*)(row + idx + 4));
    uint2  lw = *(const uint2*)(lab + idx);

    __nv_bfloat162 pdp[8]; int pls[8];
    {
        int nidx = idx + S;                       // always < CHUNK
        float4 nva = __ldcs((const float4*)(row + nidx));
        float4 nvb = __ldcs((const float4*)(row + nidx + 4));
        uint2  nlw = *(const uint2*)(lab + nidx);

        float xs[8] = {va.x, va.y, va.z, va.w, vb.x, vb.y, vb.z, vb.w};
        #pragma unroll
        for (int i = 0; i < 8; i++) {
            pls[i] = (int)(((i < 4 ? lw.x : lw.y) >> (8 * (i & 3))) & 0xffu);
            float d, p, f0;
            xform(xs[i], d, p, f0);
            if (i & 1) accf0b += f0; else accf0a += f0;
            pdp[i] = __floats2bfloat162_rn(d, p);
        }
        va = nva; vb = nvb; lw = nlw; idx = nidx;
    }

    // ---- steady state: prefetch k+1 loads; interleave xform(k) with RMW(k-1) ----
    while (idx < CHUNK) {
        int nidx = idx + S;
        float4 nva, nvb; uint2 nlw;
        if (nidx < CHUNK) {
            nva = __ldcs((const float4*)(row + nidx));
            nvb = __ldcs((const float4*)(row + nidx + 4));
            nlw = *(const uint2*)(lab + nidx);
        }

        float xs[8] = {va.x, va.y, va.z, va.w, vb.x, vb.y, vb.z, vb.w};
        int nls[8]; __nv_bfloat162 ndp[8];
        #pragma unroll
        for (int i = 0; i < 8; i++) {
            nls[i] = (int)(((i < 4 ? lw.x : lw.y) >> (8 * (i & 3))) & 0xffu);
            float d, p, f0;
            xform(xs[i], d, p, f0);          // independent work covering RMW latency
            if (i & 1) accf0b += f0; else accf0a += f0;
            ndp[i] = __floats2bfloat162_rn(d, p);
            __nv_bfloat162* bp = bbase + pls[i] * THREADS;   // RMW of PREVIOUS iter
            *bp = __hadd2(*bp, pdp[i]);
        }
        #pragma unroll
        for (int i = 0; i < 8; i++) { pls[i] = nls[i]; pdp[i] = ndp[i]; }
        va = nva; vb = nvb; lw = nlw; idx = nidx;
    }

    // ---- pipeline epilogue: flush last pending RMW ----
    #pragma unroll
    for (int i = 0; i < 8; i++) {
        __nv_bfloat162* bp = bbase + pls[i] * THREADS;
        *bp = __hadd2(*bp, pdp[i]);
    }

    float accf0 = accf0a + accf0b;
    __syncthreads();

    // reduce 128 lanes per label -> deterministic partial buffer (exact f32)
    float ss = 0.f;
    if (tid < NLAB) {
        float ds = 0.f;
        #pragma unroll 4
        for (int i = 0; i < THREADS; i++) {
            float2 v = __bfloat1622float2(sb[tid * THREADS + ((i + tid) & (THREADS - 1))]);
            ds += v.x; ss += v.y;
        }
        int o = ((r * QN + q) * NLAB + tid) * 2;
        g_partial[o]     = ds;
        g_partial[o + 1] = ss;
    }
    __syncthreads();

    // total p = sum of ss over all labels (every point has exactly one label)
    float* sred = (float*)sb;
    sred[tid] = ss;
    __syncthreads();
    #pragma unroll
    for (int s = THREADS / 2; s >= 32; s >>= 1) {
        if (tid < s) sred[tid] += sred[tid + s];
        __syncthreads();
    }
    if (tid < 32) {
        float v = sred[tid];
        #pragma unroll
        for (int off = 16; off; off >>= 1) v += __shfl_down_sync(0xffffffffu, v, off);
        if (tid == 0) g_totals[(r * QN + q) * 2 + 1] = v;
    }

    // row total f0 (exact f32 path)
    #pragma unroll
    for (int off = 16; off; off >>= 1)
        accf0 += __shfl_down_sync(0xffffffffu, accf0, off);
    __shared__ float ws[4];
    if ((tid & 31) == 0) ws[tid >> 5] = accf0;
    __syncthreads();
    if (tid == 0) {
        float f = ws[0] + ws[1] + ws[2] + ws[3];
        g_totals[(r * QN + q) * 2 + 0] = f;
    }
}

// ---------------- kernel 2: counts + cost assembly ----------------
__global__ void finalize(float* __restrict__ out) {
    const int j = blockIdx.x;           // label 0..99
    const int tid = threadIdx.x;        // 256 threads

    int c = 0;
    for (int b = tid; b < CVT_BLOCKS; b += 256)
        c += g_blockhist[b * NLAB + j];
    #pragma unroll
    for (int off = 16; off; off >>= 1) c += __shfl_down_sync(0xffffffffu, c, off);
    __shared__ int cs[8];
    if ((tid & 31) == 0) cs[tid >> 5] = c;
    __syncthreads();
    int cnt = 0;
    #pragma unroll
    for (int w = 0; w < 8; w++) cnt += cs[w];
    float fc = (float)cnt;

    for (int q = tid; q < QN; q += 256) {
        float dsum = 0.f, ssum = 0.f, f0t = 0.f, pt = 0.f;
        #pragma unroll
        for (int r = 0; r < KS; r++) {
            int bi = ((r * QN + q) * NLAB + j) * 2;
            dsum += g_partial[bi];
            ssum += g_partial[bi + 1];
            f0t  += g_totals[(r * QN + q) * 2 + 0];
            pt   += g_totals[(r * QN + q) * 2 + 1];
        }
        float cmask = (dsum + f0t) * (1.0f / (float)PN);
        float dice  = 1.0f - (2.0f * ssum + 1.0f) / (pt + fc + 1.0f);
        out[q * NLAB + j] = cmask + dice;
    }
}

// ---------------- launch ----------------
extern "C" void kernel_launch(void* const* d_in, const int* in_sizes, int n_in,
                              void* d_out, int out_size) {
    const float* pred  = (const float*)d_in[0];
    const int* labels  = (const int*)d_in[1];
    float* out = (float*)d_out;

    cudaFuncSetAttribute(main_kernel,
                         cudaFuncAttributeMaxDynamicSharedMemorySize,
                         BINW * (int)sizeof(__nv_bfloat162));

    convert_labels<<<CVT_BLOCKS, 256>>>(labels);
    dim3 grid(QN, KS);
    main_kernel<<<grid, THREADS, BINW * sizeof(__nv_bfloat162)>>>(pred);
    finalize<<<NLAB, 256>>>(out);
}

// round 9
// speedup vs baseline: 1.1989x; 1.1989x over previous
#include <cuda_runtime.h>
#include <cuda_bf16.h>

#define QN      400
#define PN      200000
#define NLAB    100
#define KS      4
#define THREADS 128
#define CHUNK   (PN / KS)                 // 50000 (divisible by 16)
#define BINW    (NLAB * THREADS)          // 12800 bf16x2 bins = 50 KB
#define CVT_BLOCKS ((PN / 4 + 255) / 256) // 196

// ---------------- device scratch (no allocation allowed) ----------------
__device__ unsigned char g_lab8[PN];
__device__ int   g_blockhist[CVT_BLOCKS * NLAB];
__device__ float g_partial[KS * QN * NLAB * 2];   // [r][q][lab][{d,s}]
__device__ float g_totals[KS * QN * 2];           // [r][q][{f0tot, ptot}]

// ---------------- kernel 0: narrow labels to u8 + per-block histogram ----------------
__global__ void convert_labels(const int* __restrict__ labels) {
    __shared__ int hist[NLAB];
    const int tid = threadIdx.x;
    for (int i = tid; i < NLAB; i += 256) hist[i] = 0;
    __syncthreads();

    int i = blockIdx.x * blockDim.x + tid;
    int base = i * 4;
    if (base < PN) {
        int4 l = *(const int4*)(labels + base);
        uchar4 u;
        u.x = (unsigned char)l.x; u.y = (unsigned char)l.y;
        u.z = (unsigned char)l.z; u.w = (unsigned char)l.w;
        *(uchar4*)(g_lab8 + base) = u;
        atomicAdd(&hist[l.x], 1); atomicAdd(&hist[l.y], 1);
        atomicAdd(&hist[l.z], 1); atomicAdd(&hist[l.w], 1);
    }
    __syncthreads();
    for (int j = tid; j < NLAB; j += 256)
        g_blockhist[blockIdx.x * NLAB + j] = hist[j];
}

// ---- branch-free transform: 3 MUFU, no selects. Safe for |x| < 80. ----
__device__ __forceinline__ void xform(float x, float& d, float& p, float& f0) {
    float t, lg;
    asm("ex2.approx.f32 %0, %1;" : "=f"(t) : "f"(x * -1.4426950408889634f)); // e^-x
    float opt = 1.0f + t;
    asm("rcp.approx.f32 %0, %1;" : "=f"(p)  : "f"(opt));   // p = sigmoid(x)
    asm("lg2.approx.f32 %0, %1;" : "=f"(lg) : "f"(opt));
    float logp = lg * -0.69314718055994531f;               // log sigmoid(x)
    float l1mp = logp - x;                                 // log sigmoid(-x)
    float omp  = t * p;                                    // 1 - p, exact identity
    f0 = (p * p) * (l1mp * -0.75f);
    float f1 = (omp * omp) * (logp * -0.25f);
    d = f1 - f0;
}

// ---------------- kernel 1: main segmented reduction (width-16, deep MLP) ----------------
__global__ __launch_bounds__(THREADS, 4)
void main_kernel(const float* __restrict__ pred) {
    extern __shared__ __nv_bfloat162 sb[];   // [NLAB][THREADS], bank = tid%32
    const int tid = threadIdx.x;
    const int q = blockIdx.x;
    const int r = blockIdx.y;

    uint4* z4 = (uint4*)sb;
    #pragma unroll 4
    for (int i = tid; i < BINW / 4; i += THREADS)
        z4[i] = make_uint4(0u, 0u, 0u, 0u);
    __syncthreads();

    const float* row = pred + (size_t)q * PN + (size_t)r * CHUNK;
    const unsigned char* lab = g_lab8 + r * CHUNK;
    __nv_bfloat162* const bbase = sb + tid;

    float accf0a = 0.f, accf0b = 0.f;
    const int S = THREADS * 16;              // 2048

    // ---- prefetch first 16-element group (4x LDG.128 pred + 1x LDG.128 labels) ----
    int idx = tid * 16;
    float4 A0, A1, A2, A3; uint4 LW;
    if (idx < CHUNK) {
        A0 = __ldcs((const float4*)(row + idx));
        A1 = __ldcs((const float4*)(row + idx + 4));
        A2 = __ldcs((const float4*)(row + idx + 8));
        A3 = __ldcs((const float4*)(row + idx + 12));
        LW = *(const uint4*)(lab + idx);
    }

    while (idx < CHUNK) {
        int nidx = idx + S;
        float4 B0, B1, B2, B3; uint4 NLW;
        if (nidx < CHUNK) {                  // loads for next group in flight during compute
            B0 = __ldcs((const float4*)(row + nidx));
            B1 = __ldcs((const float4*)(row + nidx + 4));
            B2 = __ldcs((const float4*)(row + nidx + 8));
            B3 = __ldcs((const float4*)(row + nidx + 12));
            NLW = *(const uint4*)(lab + nidx);
        }

        float xs[16] = {A0.x, A0.y, A0.z, A0.w, A1.x, A1.y, A1.z, A1.w,
                        A2.x, A2.y, A2.z, A2.w, A3.x, A3.y, A3.z, A3.w};
        unsigned lw[4] = {LW.x, LW.y, LW.z, LW.w};

        int ls[16]; __nv_bfloat162 dp[16];
        #pragma unroll
        for (int i = 0; i < 16; i++) {
            ls[i] = (int)((lw[i >> 2] >> (8 * (i & 3))) & 0xffu);
            float d, p, f0;
            xform(xs[i], d, p, f0);
            if (i & 1) accf0b += f0; else accf0a += f0;
            dp[i] = __floats2bfloat162_rn(d, p);   // .x=d, .y=p
        }
        #pragma unroll
        for (int i = 0; i < 16; i++) {
            __nv_bfloat162* bp = bbase + ls[i] * THREADS;
            *bp = __hadd2(*bp, dp[i]);
        }

        A0 = B0; A1 = B1; A2 = B2; A3 = B3; LW = NLW;
        idx = nidx;
    }

    float accf0 = accf0a + accf0b;
    __syncthreads();

    // reduce 128 lanes per label -> deterministic partial buffer (exact f32)
    float ss = 0.f;
    if (tid < NLAB) {
        float ds = 0.f;
        #pragma unroll 4
        for (int i = 0; i < THREADS; i++) {
            float2 v = __bfloat1622float2(sb[tid * THREADS + ((i + tid) & (THREADS - 1))]);
            ds += v.x; ss += v.y;
        }
        int o = ((r * QN + q) * NLAB + tid) * 2;
        g_partial[o]     = ds;
        g_partial[o + 1] = ss;
    }
    __syncthreads();

    // total p = sum of ss over all labels (every point has exactly one label)
    float* sred = (float*)sb;
    sred[tid] = ss;
    __syncthreads();
    #pragma unroll
    for (int s = THREADS / 2; s >= 32; s >>= 1) {
        if (tid < s) sred[tid] += sred[tid + s];
        __syncthreads();
    }
    if (tid < 32) {
        float v = sred[tid];
        #pragma unroll
        for (int off = 16; off; off >>= 1) v += __shfl_down_sync(0xffffffffu, v, off);
        if (tid == 0) g_totals[(r * QN + q) * 2 + 1] = v;
    }

    // row total f0 (exact f32 path)
    #pragma unroll
    for (int off = 16; off; off >>= 1)
        accf0 += __shfl_down_sync(0xffffffffu, accf0, off);
    __shared__ float ws[4];
    if ((tid & 31) == 0) ws[tid >> 5] = accf0;
    __syncthreads();
    if (tid == 0) {
        float f = ws[0] + ws[1] + ws[2] + ws[3];
        g_totals[(r * QN + q) * 2 + 0] = f;
    }
}

// ---------------- kernel 2: counts + cost assembly ----------------
__global__ void finalize(float* __restrict__ out) {
    const int j = blockIdx.x;           // label 0..99
    const int tid = threadIdx.x;        // 256 threads

    int c = 0;
    for (int b = tid; b < CVT_BLOCKS; b += 256)
        c += g_blockhist[b * NLAB + j];
    #pragma unroll
    for (int off = 16; off; off >>= 1) c += __shfl_down_sync(0xffffffffu, c, off);
    __shared__ int cs[8];
    if ((tid & 31) == 0) cs[tid >> 5] = c;
    __syncthreads();
    int cnt = 0;
    #pragma unroll
    for (int w = 0; w < 8; w++) cnt += cs[w];
    float fc = (float)cnt;

    for (int q = tid; q < QN; q += 256) {
        float dsum = 0.f, ssum = 0.f, f0t = 0.f, pt = 0.f;
        #pragma unroll
        for (int r = 0; r < KS; r++) {
            int bi = ((r * QN + q) * NLAB + j) * 2;
            dsum += g_partial[bi];
            ssum += g_partial[bi + 1];
            f0t  += g_totals[(r * QN + q) * 2 + 0];
            pt   += g_totals[(r * QN + q) * 2 + 1];
        }
        float cmask = (dsum + f0t) * (1.0f / (float)PN);
        float dice  = 1.0f - (2.0f * ssum + 1.0f) / (pt + fc + 1.0f);
        out[q * NLAB + j] = cmask + dice;
    }
}

// ---------------- launch ----------------
extern "C" void kernel_launch(void* const* d_in, const int* in_sizes, int n_in,
                              void* d_out, int out_size) {
    const float* pred  = (const float*)d_in[0];
    const int* labels  = (const int*)d_in[1];
    float* out = (float*)d_out;

    cudaFuncSetAttribute(main_kernel,
                         cudaFuncAttributeMaxDynamicSharedMemorySize,
                         BINW * (int)sizeof(__nv_bfloat162));

    convert_labels<<<CVT_BLOCKS, 256>>>(labels);
    dim3 grid(QN, KS);
    main_kernel<<<grid, THREADS, BINW * sizeof(__nv_bfloat162)>>>(pred);
    finalize<<<NLAB, 256>>>(out);
}